// round 10
// baseline (speedup 1.0000x reference)
#include <cuda_runtime.h>
#include <math.h>
#include <math_constants.h>

// GaussianMixture: out[i] = logsumexp_j ( logw_j - (x_i - mu_j)^T gamma_j (x_i - mu_j) )
// gamma = A A^T is PSD => v_ij <= logw_j: plain sum-of-exp is safe (no max pass);
// partial sums over component slices are associative.
//
// R5-shaped main blocks + single-kernel ticket finisher:
//   grid = 128 sample-groups x 8 slices = 1024 blocks of 64 threads.
//   Block (g, sl): builds slice sl's 128 coefficient sets in smem (log2e-scaled),
//   processes 512 samples (8 per thread, 4 packed f32x2 pair-groups), publishes
//   partial exp-sums to global scratch. The 8th arriving block per group combines
//   all slices, applies log - lse(w), writes out, resets the ticket (replay-safe).

#define MAX_M    1024
#define SLICES   8
#define CPS      (MAX_M / SLICES)    // 128 components per slice
#define BLOCK    64
#define SG_SAMP  512                 // samples per sample-group (64 thr * 8)
#define MAX_NSG  128                 // 65536 / 512
#define LOG2E    1.4426950408889634f

__device__ float4 g_part4[MAX_NSG * SLICES * (SG_SAMP / 4)];   // 2 MB scratch
__device__ int    g_cnt[MAX_NSG];                              // zero-initialized

__device__ __forceinline__ unsigned long long pack_f2(float lo, float hi) {
    unsigned long long r;
    asm("mov.b64 %0, {%1, %2};" : "=l"(r) : "f"(lo), "f"(hi));
    return r;
}
__device__ __forceinline__ unsigned long long fma2(unsigned long long a,
                                                   unsigned long long b,
                                                   unsigned long long c) {
    unsigned long long d;
    asm("fma.rn.f32x2 %0, %1, %2, %3;" : "=l"(d) : "l"(a), "l"(b), "l"(c));
    return d;
}
__device__ __forceinline__ unsigned long long add2(unsigned long long a,
                                                   unsigned long long b) {
    unsigned long long d;
    asm("add.rn.f32x2 %0, %1, %2;" : "=l"(d) : "l"(a), "l"(b));
    return d;
}
__device__ __forceinline__ unsigned long long mul2(unsigned long long a,
                                                   unsigned long long b) {
    unsigned long long d;
    asm("mul.rn.f32x2 %0, %1, %2;" : "=l"(d) : "l"(a), "l"(b));
    return d;
}
__device__ __forceinline__ float ex2f(float x) {
    float r;
    asm("ex2.approx.ftz.f32 %0, %1;" : "=f"(r) : "f"(x));
    return r;
}

__global__ void __launch_bounds__(BLOCK, 7)
gm_kernel(const float4* __restrict__ sample4,
          const float* __restrict__ mu,
          const float4* __restrict__ A4,
          const float* __restrict__ w,
          float* __restrict__ out,
          int N, int M)
{
    // slice coeffs: comp c -> {(k0,k0),(k1,k1)},{(k2,k2),(k3,k3)},{(k4,k4),(k5,k5)}
    __shared__ ulonglong2 sc[CPS * 3];   // 6 KB
    __shared__ int s_old;

    int sg   = blockIdx.x >> 3;            // sample-group id
    int sl   = blockIdx.x & (SLICES - 1);  // component slice id
    int tid  = threadIdx.x;
    int lane = tid & 31;

    // ---- prologue: 128-comp slice coefficients (2 comps/thread) ----
    #pragma unroll
    for (int c = tid; c < CPS; c += BLOCK) {
        int j = sl * CPS + c;
        if (j < M) {
            float4 Aj = A4[j];
            float a00 = Aj.x, a01 = Aj.y, a10 = Aj.z, a11 = Aj.w;

            float g00 = a00*a00 + a01*a01;
            float g01 = a00*a10 + a01*a11;
            float g11 = a10*a10 + a11*a11;

            float det = g00*g11 - g01*g01;
            float m0 = mu[j*2 + 0], m1 = mu[j*2 + 1];
            float gm0 = g00*m0 + g01*m1;
            float gm1 = g01*m0 + g11*m1;
            float mGm = gm0*m0 + gm1*m1;

            float k0 = fmaf(w[j] - mGm, LOG2E, 0.5f * __log2f(det));
            float k1 = ( 2.0f * gm0) * LOG2E;
            float k2 = ( 2.0f * gm1) * LOG2E;
            float k3 = (-g00)        * LOG2E;
            float k4 = (-2.0f * g01) * LOG2E;
            float k5 = (-g11)        * LOG2E;

            sc[c*3 + 0] = make_ulonglong2(pack_f2(k0, k0), pack_f2(k1, k1));
            sc[c*3 + 1] = make_ulonglong2(pack_f2(k2, k2), pack_f2(k3, k3));
            sc[c*3 + 2] = make_ulonglong2(pack_f2(k4, k4), pack_f2(k5, k5));
        }
    }
    __syncthreads();

    // ---- main loop: 8 samples/thread over this 128-comp slice ----
    int s0i = sg * SG_SAMP + tid * 8;       // first SAMPLE of this thread
    int f4i = s0i >> 1;                     // 2 samples per float4
    float4 xa = sample4[f4i + 0];
    float4 xb = sample4[f4i + 1];
    float4 xc = sample4[f4i + 2];
    float4 xd = sample4[f4i + 3];

    unsigned long long A0 = pack_f2(xa.x, xa.z), A1 = pack_f2(xa.y, xa.w);
    unsigned long long B0 = pack_f2(xb.x, xb.z), B1 = pack_f2(xb.y, xb.w);
    unsigned long long C0 = pack_f2(xc.x, xc.z), C1 = pack_f2(xc.y, xc.w);
    unsigned long long D0 = pack_f2(xd.x, xd.z), D1 = pack_f2(xd.y, xd.w);

    unsigned long long A2 = mul2(A0, A0), A3 = mul2(A0, A1), A4_ = mul2(A1, A1);
    unsigned long long B2 = mul2(B0, B0), B3 = mul2(B0, B1), B4 = mul2(B1, B1);
    unsigned long long C2 = mul2(C0, C0), C3 = mul2(C0, C1), C4 = mul2(C1, C1);
    unsigned long long D2 = mul2(D0, D0), D3 = mul2(D0, D1), D4 = mul2(D1, D1);

    unsigned long long sA = 0ull, sB = 0ull, sC = 0ull, sD = 0ull;

    #pragma unroll 2
    for (int j = 0; j < CPS; j++) {
        ulonglong2 e0 = sc[j*3 + 0];
        ulonglong2 e1 = sc[j*3 + 1];
        ulonglong2 e2 = sc[j*3 + 2];

        unsigned long long vA, vB, vC, vD;
        vA = fma2(A0, e0.y, e0.x);
        vB = fma2(B0, e0.y, e0.x);
        vC = fma2(C0, e0.y, e0.x);
        vD = fma2(D0, e0.y, e0.x);
        vA = fma2(A1, e1.x, vA);
        vB = fma2(B1, e1.x, vB);
        vC = fma2(C1, e1.x, vC);
        vD = fma2(D1, e1.x, vD);
        vA = fma2(A2, e1.y, vA);
        vB = fma2(B2, e1.y, vB);
        vC = fma2(C2, e1.y, vC);
        vD = fma2(D2, e1.y, vD);
        vA = fma2(A3, e2.x, vA);
        vB = fma2(B3, e2.x, vB);
        vC = fma2(C3, e2.x, vC);
        vD = fma2(D3, e2.x, vD);
        vA = fma2(A4_, e2.y, vA);
        vB = fma2(B4,  e2.y, vB);
        vC = fma2(C4,  e2.y, vC);
        vD = fma2(D4,  e2.y, vD);

        float v0, v1, v2, v3, v4, v5, v6, v7;
        asm("mov.b64 {%0, %1}, %2;" : "=f"(v0), "=f"(v1) : "l"(vA));
        asm("mov.b64 {%0, %1}, %2;" : "=f"(v2), "=f"(v3) : "l"(vB));
        asm("mov.b64 {%0, %1}, %2;" : "=f"(v4), "=f"(v5) : "l"(vC));
        asm("mov.b64 {%0, %1}, %2;" : "=f"(v6), "=f"(v7) : "l"(vD));

        sA = add2(sA, pack_f2(ex2f(v0), ex2f(v1)));
        sB = add2(sB, pack_f2(ex2f(v2), ex2f(v3)));
        sC = add2(sC, pack_f2(ex2f(v4), ex2f(v5)));
        sD = add2(sD, pack_f2(ex2f(v6), ex2f(v7)));
    }

    float s0, s1, s2, s3, s4, s5, s6, s7;
    asm("mov.b64 {%0, %1}, %2;" : "=f"(s0), "=f"(s1) : "l"(sA));
    asm("mov.b64 {%0, %1}, %2;" : "=f"(s2), "=f"(s3) : "l"(sB));
    asm("mov.b64 {%0, %1}, %2;" : "=f"(s4), "=f"(s5) : "l"(sC));
    asm("mov.b64 {%0, %1}, %2;" : "=f"(s6), "=f"(s7) : "l"(sD));

    // ---- publish partials (coalesced) and take a ticket ----
    int pbase = (sg * SLICES + sl) * (SG_SAMP / 4) + tid * 2;
    g_part4[pbase + 0] = make_float4(s0, s1, s2, s3);
    g_part4[pbase + 1] = make_float4(s4, s5, s6, s7);
    __threadfence();
    __syncthreads();   // all 64 threads' stores are fenced before the ticket
    if (tid == 0) s_old = atomicAdd(&g_cnt[sg], 1);
    __syncthreads();
    if (s_old != SLICES - 1) return;

    // ---- finisher: all 8 slices published for this group ----
    __threadfence();

    // lse over w (each warp redundantly; 32 values per lane)
    float mx = -CUDART_INF_F;
    for (int k = lane; k < M; k += 32) mx = fmaxf(mx, w[k]);
    #pragma unroll
    for (int s = 16; s > 0; s >>= 1) mx = fmaxf(mx, __shfl_xor_sync(~0u, mx, s));
    float e = 0.0f;
    for (int k = lane; k < M; k += 32) e += __expf(w[k] - mx);
    #pragma unroll
    for (int s = 16; s > 0; s >>= 1) e += __shfl_xor_sync(~0u, e, s);
    float lse_w = mx + logf(e);

    // combine slices for this thread's 8 samples
    float acc0 = 0.f, acc1 = 0.f, acc2 = 0.f, acc3 = 0.f;
    float acc4 = 0.f, acc5 = 0.f, acc6 = 0.f, acc7 = 0.f;
    #pragma unroll
    for (int g = 0; g < SLICES; g++) {
        int b2 = (sg * SLICES + g) * (SG_SAMP / 4) + tid * 2;
        float4 q0 = g_part4[b2 + 0];
        float4 q1 = g_part4[b2 + 1];
        acc0 += q0.x; acc1 += q0.y; acc2 += q0.z; acc3 += q0.w;
        acc4 += q1.x; acc5 += q1.y; acc6 += q1.z; acc7 += q1.w;
    }

    if (s0i + 7 < N) {
        float4* o4 = reinterpret_cast<float4*>(out);
        o4[(s0i >> 2) + 0] = make_float4(logf(acc0) - lse_w, logf(acc1) - lse_w,
                                         logf(acc2) - lse_w, logf(acc3) - lse_w);
        o4[(s0i >> 2) + 1] = make_float4(logf(acc4) - lse_w, logf(acc5) - lse_w,
                                         logf(acc6) - lse_w, logf(acc7) - lse_w);
    }

    __syncthreads();                 // all finisher reads done
    if (tid == 0) g_cnt[sg] = 0;     // reset ticket for next graph replay
}

extern "C" void kernel_launch(void* const* d_in, const int* in_sizes, int n_in,
                              void* d_out, int out_size)
{
    const float* sample = (const float*)d_in[0];   // (N, 2)
    const float* mu     = (const float*)d_in[1];   // (M, 2)
    const float* A      = (const float*)d_in[2];   // (M, 2, 2)
    const float* w      = (const float*)d_in[3];   // (M, 1)
    float* out = (float*)d_out;

    int N = in_sizes[0] / 2;
    int M = in_sizes[3];
    if (M > MAX_M) M = MAX_M;

    int nsg  = (N + SG_SAMP - 1) / SG_SAMP;        // 128 sample-groups
    int grid = nsg * SLICES;                       // 1024 blocks of 64 threads
    gm_kernel<<<grid, BLOCK>>>((const float4*)sample, mu, (const float4*)A,
                               w, out, N, M);
}

// round 11
// speedup vs baseline: 1.0556x; 1.0556x over previous
#include <cuda_runtime.h>
#include <math.h>
#include <math_constants.h>

// GaussianMixture: out[i] = logsumexp_j ( logw_j - (x_i - mu_j)^T gamma_j (x_i - mu_j) )
// gamma = A A^T is PSD => v_ij <= logw_j: plain sum-of-exp is safe (no max pass);
// partial sums over component slices are associative.
//
// Two kernels (fused ticket variants measured slower due to GPU-scope fences):
//  1) gm_kernel: grid = 128 sample-groups x 8 slices interleaved = 1024 blocks x 64
//     threads; block (g, sl) builds slice sl's 128 coefficient sets in smem
//     (log2e-scaled so exp = ex2), processes 512 samples (8/thread via packed f32x2),
//     writes partial exp-sums to a global slice buffer (plain STG.128, no atomics).
//  2) finalize_kernel: 4 samples/thread (float4), combines 8 slices,
//     out = (log2(sum) - lse_w*log2e) * ln2  -- one MUFU.LG2 per sample.

#define MAX_M    1024
#define MAX_N    65536
#define SLICES   8
#define CPS      (MAX_M / SLICES)    // 128 components per slice
#define GM_BLOCK 64
#define LOG2E    1.4426950408889634f
#define LN2      0.6931471805599453f

__device__ float g_part[SLICES][MAX_N];   // 2 MB scratch (L2-resident)

__device__ __forceinline__ unsigned long long pack_f2(float lo, float hi) {
    unsigned long long r;
    asm("mov.b64 %0, {%1, %2};" : "=l"(r) : "f"(lo), "f"(hi));
    return r;
}
__device__ __forceinline__ unsigned long long fma2(unsigned long long a,
                                                   unsigned long long b,
                                                   unsigned long long c) {
    unsigned long long d;
    asm("fma.rn.f32x2 %0, %1, %2, %3;" : "=l"(d) : "l"(a), "l"(b), "l"(c));
    return d;
}
__device__ __forceinline__ unsigned long long add2(unsigned long long a,
                                                   unsigned long long b) {
    unsigned long long d;
    asm("add.rn.f32x2 %0, %1, %2;" : "=l"(d) : "l"(a), "l"(b));
    return d;
}
__device__ __forceinline__ unsigned long long mul2(unsigned long long a,
                                                   unsigned long long b) {
    unsigned long long d;
    asm("mul.rn.f32x2 %0, %1, %2;" : "=l"(d) : "l"(a), "l"(b));
    return d;
}
__device__ __forceinline__ float ex2f(float x) {
    float r;
    asm("ex2.approx.ftz.f32 %0, %1;" : "=f"(r) : "f"(x));
    return r;
}
__device__ __forceinline__ float lg2f(float x) {
    float r;
    asm("lg2.approx.ftz.f32 %0, %1;" : "=f"(r) : "f"(x));
    return r;
}

__global__ void __launch_bounds__(GM_BLOCK, 7)
gm_kernel(const float4* __restrict__ sample4,
          const float* __restrict__ mu,
          const float* __restrict__ A,
          const float* __restrict__ w,
          int nocts, int M)
{
    // slice coeffs: comp c -> {(k0,k0),(k1,k1)},{(k2,k2),(k3,k3)},{(k4,k4),(k5,k5)}
    __shared__ ulonglong2 sc[CPS * 3];   // 6 KB

    int slice  = blockIdx.x & (SLICES - 1);
    int blk    = blockIdx.x >> 3;
    int tid    = threadIdx.x;
    int jbase  = slice * CPS;

    // ---- prologue: this slice's coefficients (2 comps/thread) ----
    #pragma unroll
    for (int c = tid; c < CPS; c += GM_BLOCK) {
        int j = jbase + c;
        float a00 = A[j*4 + 0], a01 = A[j*4 + 1];
        float a10 = A[j*4 + 2], a11 = A[j*4 + 3];

        float g00 = a00*a00 + a01*a01;
        float g01 = a00*a10 + a01*a11;
        float g11 = a10*a10 + a11*a11;

        float det = g00*g11 - g01*g01;
        float m0 = mu[j*2 + 0], m1 = mu[j*2 + 1];
        float gm0 = g00*m0 + g01*m1;
        float gm1 = g01*m0 + g11*m1;
        float mGm = gm0*m0 + gm1*m1;

        float k0 = fmaf(w[j] - mGm, LOG2E, 0.5f * __log2f(det));
        float k1 = ( 2.0f * gm0) * LOG2E;
        float k2 = ( 2.0f * gm1) * LOG2E;
        float k3 = (-g00)        * LOG2E;
        float k4 = (-2.0f * g01) * LOG2E;
        float k5 = (-g11)        * LOG2E;

        sc[c*3 + 0] = make_ulonglong2(pack_f2(k0, k0), pack_f2(k1, k1));
        sc[c*3 + 1] = make_ulonglong2(pack_f2(k2, k2), pack_f2(k3, k3));
        sc[c*3 + 2] = make_ulonglong2(pack_f2(k4, k4), pack_f2(k5, k5));
    }
    __syncthreads();

    int t = blk * GM_BLOCK + tid;     // one thread = 8 samples (one oct)
    if (t >= nocts) return;

    float4 xa = sample4[4*t + 0];
    float4 xb = sample4[4*t + 1];
    float4 xc = sample4[4*t + 2];
    float4 xd = sample4[4*t + 3];

    unsigned long long A0 = pack_f2(xa.x, xa.z), A1 = pack_f2(xa.y, xa.w);
    unsigned long long B0 = pack_f2(xb.x, xb.z), B1 = pack_f2(xb.y, xb.w);
    unsigned long long C0 = pack_f2(xc.x, xc.z), C1 = pack_f2(xc.y, xc.w);
    unsigned long long D0 = pack_f2(xd.x, xd.z), D1 = pack_f2(xd.y, xd.w);

    unsigned long long A2 = mul2(A0, A0), A3 = mul2(A0, A1), A4 = mul2(A1, A1);
    unsigned long long B2 = mul2(B0, B0), B3 = mul2(B0, B1), B4 = mul2(B1, B1);
    unsigned long long C2 = mul2(C0, C0), C3 = mul2(C0, C1), C4 = mul2(C1, C1);
    unsigned long long D2 = mul2(D0, D0), D3 = mul2(D0, D1), D4 = mul2(D1, D1);

    unsigned long long sA = 0ull, sB = 0ull, sC = 0ull, sD = 0ull;

    #pragma unroll 2
    for (int j = 0; j < CPS; j++) {
        ulonglong2 e0 = sc[j*3 + 0];
        ulonglong2 e1 = sc[j*3 + 1];
        ulonglong2 e2 = sc[j*3 + 2];

        unsigned long long vA, vB, vC, vD;
        vA = fma2(A0, e0.y, e0.x);
        vB = fma2(B0, e0.y, e0.x);
        vC = fma2(C0, e0.y, e0.x);
        vD = fma2(D0, e0.y, e0.x);
        vA = fma2(A1, e1.x, vA);
        vB = fma2(B1, e1.x, vB);
        vC = fma2(C1, e1.x, vC);
        vD = fma2(D1, e1.x, vD);
        vA = fma2(A2, e1.y, vA);
        vB = fma2(B2, e1.y, vB);
        vC = fma2(C2, e1.y, vC);
        vD = fma2(D2, e1.y, vD);
        vA = fma2(A3, e2.x, vA);
        vB = fma2(B3, e2.x, vB);
        vC = fma2(C3, e2.x, vC);
        vD = fma2(D3, e2.x, vD);
        vA = fma2(A4, e2.y, vA);
        vB = fma2(B4, e2.y, vB);
        vC = fma2(C4, e2.y, vC);
        vD = fma2(D4, e2.y, vD);

        float v0, v1, v2, v3, v4, v5, v6, v7;
        asm("mov.b64 {%0, %1}, %2;" : "=f"(v0), "=f"(v1) : "l"(vA));
        asm("mov.b64 {%0, %1}, %2;" : "=f"(v2), "=f"(v3) : "l"(vB));
        asm("mov.b64 {%0, %1}, %2;" : "=f"(v4), "=f"(v5) : "l"(vC));
        asm("mov.b64 {%0, %1}, %2;" : "=f"(v6), "=f"(v7) : "l"(vD));

        sA = add2(sA, pack_f2(ex2f(v0), ex2f(v1)));
        sB = add2(sB, pack_f2(ex2f(v2), ex2f(v3)));
        sC = add2(sC, pack_f2(ex2f(v4), ex2f(v5)));
        sD = add2(sD, pack_f2(ex2f(v6), ex2f(v7)));
    }

    float s0, s1, s2, s3, s4, s5, s6, s7;
    asm("mov.b64 {%0, %1}, %2;" : "=f"(s0), "=f"(s1) : "l"(sA));
    asm("mov.b64 {%0, %1}, %2;" : "=f"(s2), "=f"(s3) : "l"(sB));
    asm("mov.b64 {%0, %1}, %2;" : "=f"(s4), "=f"(s5) : "l"(sC));
    asm("mov.b64 {%0, %1}, %2;" : "=f"(s6), "=f"(s7) : "l"(sD));

    float4* dst = reinterpret_cast<float4*>(&g_part[slice][8*t]);
    dst[0] = make_float4(s0, s1, s2, s3);
    dst[1] = make_float4(s4, s5, s6, s7);
}

// finalize: 4 samples/thread; combine 8 slices, out = (lg2(s) - lse_w*log2e)*ln2.
#define FZ_BLOCK 256

__global__ void __launch_bounds__(FZ_BLOCK)
finalize_kernel(const float* __restrict__ w,
                float* __restrict__ out, int N, int M)
{
    __shared__ float red[FZ_BLOCK / 32];
    int tid  = threadIdx.x;
    int lane = tid & 31;
    int wrp  = tid >> 5;

    // lse over w: 4 elems/thread (M <= 1024)
    float w0 = (tid        < M) ? w[tid]        : -CUDART_INF_F;
    float w1 = (tid + 256  < M) ? w[tid + 256]  : -CUDART_INF_F;
    float w2 = (tid + 512  < M) ? w[tid + 512]  : -CUDART_INF_F;
    float w3 = (tid + 768  < M) ? w[tid + 768]  : -CUDART_INF_F;

    float mx = fmaxf(fmaxf(w0, w1), fmaxf(w2, w3));
    #pragma unroll
    for (int s = 16; s > 0; s >>= 1) mx = fmaxf(mx, __shfl_xor_sync(~0u, mx, s));
    if (lane == 0) red[wrp] = mx;
    __syncthreads();
    float wmax = red[0];
    #pragma unroll
    for (int k = 1; k < FZ_BLOCK / 32; k++) wmax = fmaxf(wmax, red[k]);
    __syncthreads();

    float e = 0.0f;
    if (tid        < M) e += __expf(w0 - wmax);
    if (tid + 256  < M) e += __expf(w1 - wmax);
    if (tid + 512  < M) e += __expf(w2 - wmax);
    if (tid + 768  < M) e += __expf(w3 - wmax);
    #pragma unroll
    for (int s = 16; s > 0; s >>= 1) e += __shfl_xor_sync(~0u, e, s);
    if (lane == 0) red[wrp] = e;
    __syncthreads();
    float esum = red[0];
    #pragma unroll
    for (int k = 1; k < FZ_BLOCK / 32; k++) esum += red[k];
    float lse2 = fmaf(wmax, LOG2E, lg2f(esum));   // lse_w in log2 units

    // combine slices: 4 samples per thread via float4
    int i4 = blockIdx.x * FZ_BLOCK + tid;          // float4 index
    if (i4 * 4 >= N) return;

    float4 acc = make_float4(0.f, 0.f, 0.f, 0.f);
    #pragma unroll
    for (int k = 0; k < SLICES; k++) {
        float4 q = reinterpret_cast<const float4*>(&g_part[k][0])[i4];
        acc.x += q.x; acc.y += q.y; acc.z += q.z; acc.w += q.w;
    }

    float4 o;
    o.x = (lg2f(acc.x) - lse2) * LN2;
    o.y = (lg2f(acc.y) - lse2) * LN2;
    o.z = (lg2f(acc.z) - lse2) * LN2;
    o.w = (lg2f(acc.w) - lse2) * LN2;
    reinterpret_cast<float4*>(out)[i4] = o;
}

extern "C" void kernel_launch(void* const* d_in, const int* in_sizes, int n_in,
                              void* d_out, int out_size)
{
    const float* sample = (const float*)d_in[0];   // (N, 2)
    const float* mu     = (const float*)d_in[1];   // (M, 2)
    const float* A      = (const float*)d_in[2];   // (M, 2, 2)
    const float* w      = (const float*)d_in[3];   // (M, 1)
    float* out = (float*)d_out;

    int N = in_sizes[0] / 2;
    int M = in_sizes[3];
    if (M > MAX_M) M = MAX_M;
    if (N > MAX_N) N = MAX_N;

    int nocts = N / 8;
    int blocks_per_slice = (nocts + GM_BLOCK - 1) / GM_BLOCK;
    gm_kernel<<<blocks_per_slice * SLICES, GM_BLOCK>>>(
        (const float4*)sample, mu, A, w, nocts, M);

    int fz_grid = (N / 4 + FZ_BLOCK - 1) / FZ_BLOCK;
    finalize_kernel<<<fz_grid, FZ_BLOCK>>>(w, out, N, M);
}

// round 12
// speedup vs baseline: 1.0767x; 1.0201x over previous
#include <cuda_runtime.h>
#include <math.h>
#include <math_constants.h>

// GaussianMixture: out[i] = logsumexp_j ( logw_j - (x_i - mu_j)^T gamma_j (x_i - mu_j) )
// gamma = A A^T is PSD => v_ij <= logw_j: plain sum-of-exp is safe (no max pass);
// partial sums over component slices are associative.
//
// Two kernels:
//  1) gm_kernel: grid = 128 sample-groups x 8 slices = 1024 blocks x 64 threads.
//     Prologue: redundant per-block lse(w) (shuffle+smem reduce, L2-hot) folded into
//     k0, then this slice's 128 coefficient sets in smem (log2e-scaled so exp = ex2).
//     Main loop: 512 samples/block (8/thread via packed f32x2), partial exp-sums to
//     a global slice buffer (plain STG.128).
//  2) finalize_kernel: PURE combine -- 8 independent float4 loads, sum, lg2*ln2,
//     store. No reductions, no barriers (lse_w already inside k0).

#define MAX_M    1024
#define MAX_N    65536
#define SLICES   8
#define CPS      (MAX_M / SLICES)    // 128 components per slice
#define GM_BLOCK 64
#define LOG2E    1.4426950408889634f
#define LN2      0.6931471805599453f

__device__ float g_part[SLICES][MAX_N];   // 2 MB scratch (L2-resident)

__device__ __forceinline__ unsigned long long pack_f2(float lo, float hi) {
    unsigned long long r;
    asm("mov.b64 %0, {%1, %2};" : "=l"(r) : "f"(lo), "f"(hi));
    return r;
}
__device__ __forceinline__ unsigned long long fma2(unsigned long long a,
                                                   unsigned long long b,
                                                   unsigned long long c) {
    unsigned long long d;
    asm("fma.rn.f32x2 %0, %1, %2, %3;" : "=l"(d) : "l"(a), "l"(b), "l"(c));
    return d;
}
__device__ __forceinline__ unsigned long long add2(unsigned long long a,
                                                   unsigned long long b) {
    unsigned long long d;
    asm("add.rn.f32x2 %0, %1, %2;" : "=l"(d) : "l"(a), "l"(b));
    return d;
}
__device__ __forceinline__ unsigned long long mul2(unsigned long long a,
                                                   unsigned long long b) {
    unsigned long long d;
    asm("mul.rn.f32x2 %0, %1, %2;" : "=l"(d) : "l"(a), "l"(b));
    return d;
}
__device__ __forceinline__ float ex2f(float x) {
    float r;
    asm("ex2.approx.ftz.f32 %0, %1;" : "=f"(r) : "f"(x));
    return r;
}
__device__ __forceinline__ float lg2f(float x) {
    float r;
    asm("lg2.approx.ftz.f32 %0, %1;" : "=f"(r) : "f"(x));
    return r;
}

__global__ void __launch_bounds__(GM_BLOCK, 7)
gm_kernel(const float4* __restrict__ sample4,
          const float* __restrict__ mu,
          const float* __restrict__ A,
          const float* __restrict__ w,
          int nocts, int M)
{
    // slice coeffs: comp c -> {(k0,k0),(k1,k1)},{(k2,k2),(k3,k3)},{(k4,k4),(k5,k5)}
    __shared__ ulonglong2 sc[CPS * 3];   // 6 KB
    __shared__ float red[2];

    int slice  = blockIdx.x & (SLICES - 1);
    int blk    = blockIdx.x >> 3;
    int tid    = threadIdx.x;
    int lane   = tid & 31;
    int wrp    = tid >> 5;
    int jbase  = slice * CPS;

    // ---- prologue A: lse over w (redundant per block; 16 elems/thread) ----
    float wv[16];
    float mx = -CUDART_INF_F;
    #pragma unroll
    for (int k = 0; k < 16; k++) {
        int idx = tid + k * GM_BLOCK;
        wv[k] = (idx < M) ? w[idx] : -CUDART_INF_F;
        mx = fmaxf(mx, wv[k]);
    }
    #pragma unroll
    for (int s = 16; s > 0; s >>= 1) mx = fmaxf(mx, __shfl_xor_sync(~0u, mx, s));
    if (lane == 0) red[wrp] = mx;
    __syncthreads();
    float wmax = fmaxf(red[0], red[1]);
    __syncthreads();

    float e = 0.0f;
    #pragma unroll
    for (int k = 0; k < 16; k++)
        if (tid + k * GM_BLOCK < M) e += __expf(wv[k] - wmax);
    #pragma unroll
    for (int s = 16; s > 0; s >>= 1) e += __shfl_xor_sync(~0u, e, s);
    if (lane == 0) red[wrp] = e;
    __syncthreads();
    // lse_w in log2 units
    float lse2 = fmaf(wmax, LOG2E, lg2f(red[0] + red[1]));

    // ---- prologue B: this slice's coefficients (2 comps/thread) ----
    #pragma unroll
    for (int c = tid; c < CPS; c += GM_BLOCK) {
        int j = jbase + c;
        float a00 = A[j*4 + 0], a01 = A[j*4 + 1];
        float a10 = A[j*4 + 2], a11 = A[j*4 + 3];

        float g00 = a00*a00 + a01*a01;
        float g01 = a00*a10 + a01*a11;
        float g11 = a10*a10 + a11*a11;

        float det = g00*g11 - g01*g01;
        float m0 = mu[j*2 + 0], m1 = mu[j*2 + 1];
        float gm0 = g00*m0 + g01*m1;
        float gm1 = g01*m0 + g11*m1;
        float mGm = gm0*m0 + gm1*m1;

        // k0 includes -lse_w (log2 units): exp-sums are fully normalized
        float k0 = fmaf(w[j] - mGm, LOG2E, 0.5f * __log2f(det)) - lse2;
        float k1 = ( 2.0f * gm0) * LOG2E;
        float k2 = ( 2.0f * gm1) * LOG2E;
        float k3 = (-g00)        * LOG2E;
        float k4 = (-2.0f * g01) * LOG2E;
        float k5 = (-g11)        * LOG2E;

        sc[c*3 + 0] = make_ulonglong2(pack_f2(k0, k0), pack_f2(k1, k1));
        sc[c*3 + 1] = make_ulonglong2(pack_f2(k2, k2), pack_f2(k3, k3));
        sc[c*3 + 2] = make_ulonglong2(pack_f2(k4, k4), pack_f2(k5, k5));
    }
    __syncthreads();

    int t = blk * GM_BLOCK + tid;     // one thread = 8 samples (one oct)
    if (t >= nocts) return;

    float4 xa = sample4[4*t + 0];
    float4 xb = sample4[4*t + 1];
    float4 xc = sample4[4*t + 2];
    float4 xd = sample4[4*t + 3];

    unsigned long long A0 = pack_f2(xa.x, xa.z), A1 = pack_f2(xa.y, xa.w);
    unsigned long long B0 = pack_f2(xb.x, xb.z), B1 = pack_f2(xb.y, xb.w);
    unsigned long long C0 = pack_f2(xc.x, xc.z), C1 = pack_f2(xc.y, xc.w);
    unsigned long long D0 = pack_f2(xd.x, xd.z), D1 = pack_f2(xd.y, xd.w);

    unsigned long long A2 = mul2(A0, A0), A3 = mul2(A0, A1), A4 = mul2(A1, A1);
    unsigned long long B2 = mul2(B0, B0), B3 = mul2(B0, B1), B4 = mul2(B1, B1);
    unsigned long long C2 = mul2(C0, C0), C3 = mul2(C0, C1), C4 = mul2(C1, C1);
    unsigned long long D2 = mul2(D0, D0), D3 = mul2(D0, D1), D4 = mul2(D1, D1);

    unsigned long long sA = 0ull, sB = 0ull, sC = 0ull, sD = 0ull;

    #pragma unroll 2
    for (int j = 0; j < CPS; j++) {
        ulonglong2 e0 = sc[j*3 + 0];
        ulonglong2 e1 = sc[j*3 + 1];
        ulonglong2 e2 = sc[j*3 + 2];

        unsigned long long vA, vB, vC, vD;
        vA = fma2(A0, e0.y, e0.x);
        vB = fma2(B0, e0.y, e0.x);
        vC = fma2(C0, e0.y, e0.x);
        vD = fma2(D0, e0.y, e0.x);
        vA = fma2(A1, e1.x, vA);
        vB = fma2(B1, e1.x, vB);
        vC = fma2(C1, e1.x, vC);
        vD = fma2(D1, e1.x, vD);
        vA = fma2(A2, e1.y, vA);
        vB = fma2(B2, e1.y, vB);
        vC = fma2(C2, e1.y, vC);
        vD = fma2(D2, e1.y, vD);
        vA = fma2(A3, e2.x, vA);
        vB = fma2(B3, e2.x, vB);
        vC = fma2(C3, e2.x, vC);
        vD = fma2(D3, e2.x, vD);
        vA = fma2(A4, e2.y, vA);
        vB = fma2(B4, e2.y, vB);
        vC = fma2(C4, e2.y, vC);
        vD = fma2(D4, e2.y, vD);

        float v0, v1, v2, v3, v4, v5, v6, v7;
        asm("mov.b64 {%0, %1}, %2;" : "=f"(v0), "=f"(v1) : "l"(vA));
        asm("mov.b64 {%0, %1}, %2;" : "=f"(v2), "=f"(v3) : "l"(vB));
        asm("mov.b64 {%0, %1}, %2;" : "=f"(v4), "=f"(v5) : "l"(vC));
        asm("mov.b64 {%0, %1}, %2;" : "=f"(v6), "=f"(v7) : "l"(vD));

        sA = add2(sA, pack_f2(ex2f(v0), ex2f(v1)));
        sB = add2(sB, pack_f2(ex2f(v2), ex2f(v3)));
        sC = add2(sC, pack_f2(ex2f(v4), ex2f(v5)));
        sD = add2(sD, pack_f2(ex2f(v6), ex2f(v7)));
    }

    float s0, s1, s2, s3, s4, s5, s6, s7;
    asm("mov.b64 {%0, %1}, %2;" : "=f"(s0), "=f"(s1) : "l"(sA));
    asm("mov.b64 {%0, %1}, %2;" : "=f"(s2), "=f"(s3) : "l"(sB));
    asm("mov.b64 {%0, %1}, %2;" : "=f"(s4), "=f"(s5) : "l"(sC));
    asm("mov.b64 {%0, %1}, %2;" : "=f"(s6), "=f"(s7) : "l"(sD));

    float4* dst = reinterpret_cast<float4*>(&g_part[slice][8*t]);
    dst[0] = make_float4(s0, s1, s2, s3);
    dst[1] = make_float4(s4, s5, s6, s7);
}

// finalize: PURE combine -- 8 float4 loads (MLP=8), sum, log, store. No reductions.
#define FZ_BLOCK 128

__global__ void __launch_bounds__(FZ_BLOCK)
finalize_kernel(float* __restrict__ out, int N)
{
    int i4 = blockIdx.x * FZ_BLOCK + threadIdx.x;   // float4 index (4 samples)
    if (i4 * 4 >= N) return;

    float4 acc = make_float4(0.f, 0.f, 0.f, 0.f);
    #pragma unroll
    for (int k = 0; k < SLICES; k++) {
        float4 q = reinterpret_cast<const float4*>(&g_part[k][0])[i4];
        acc.x += q.x; acc.y += q.y; acc.z += q.z; acc.w += q.w;
    }

    float4 o;
    o.x = lg2f(acc.x) * LN2;
    o.y = lg2f(acc.y) * LN2;
    o.z = lg2f(acc.z) * LN2;
    o.w = lg2f(acc.w) * LN2;
    reinterpret_cast<float4*>(out)[i4] = o;
}

extern "C" void kernel_launch(void* const* d_in, const int* in_sizes, int n_in,
                              void* d_out, int out_size)
{
    const float* sample = (const float*)d_in[0];   // (N, 2)
    const float* mu     = (const float*)d_in[1];   // (M, 2)
    const float* A      = (const float*)d_in[2];   // (M, 2, 2)
    const float* w      = (const float*)d_in[3];   // (M, 1)
    float* out = (float*)d_out;

    int N = in_sizes[0] / 2;
    int M = in_sizes[3];
    if (M > MAX_M) M = MAX_M;
    if (N > MAX_N) N = MAX_N;

    int nocts = N / 8;
    int blocks_per_slice = (nocts + GM_BLOCK - 1) / GM_BLOCK;
    gm_kernel<<<blocks_per_slice * SLICES, GM_BLOCK>>>(
        (const float4*)sample, mu, A, w, nocts, M);

    int fz_grid = (N / 4 + FZ_BLOCK - 1) / FZ_BLOCK;
    finalize_kernel<<<fz_grid, FZ_BLOCK>>>(out, N);
}